// round 14
// baseline (speedup 1.0000x reference)
#include <cuda_runtime.h>
#include <cuda_bf16.h>
#include <cuda_fp16.h>

// Problem constants (fixed by the dataset).
#define NMAX 50000
#define CAP  64           // max in-degree bucket (Poisson mean 25; P(>64)~e-107)
#define DH   64
#define BGR  512

// ---------------- scratch (static device memory; no allocations) -----------
__device__ int     g_cnt [NMAX];                  // in-degree (excl. self loop)
__device__ int     g_csr [(size_t)NMAX * CAP];    // bucketed incoming src lists
__device__ __half2 g_h1  [(size_t)NMAX * 32];     // layer outputs (ping, fp16)
__device__ __half2 g_h2  [(size_t)NMAX * 32];     // layer outputs (pong, fp16)
__device__ __half2 g_g   [(size_t)NMAX * 32];     // dinv-scaled GEMM output
__device__ float   g_pool[BGR * DH];              // per-graph feature sums
__device__ int     g_pcnt[BGR];                   // per-graph node counts

// ---------------- setup kernels --------------------------------------------
__global__ void zero_kernel(int n) {
    int i = blockIdx.x * blockDim.x + threadIdx.x;
    if (i < n)        g_cnt[i]  = 0;
    if (i < BGR * DH) g_pool[i] = 0.0f;
    if (i < BGR)      g_pcnt[i] = 0;
}

__global__ void csr_build_kernel(const int* __restrict__ ei, int e_count) {
    int e = blockIdx.x * blockDim.x + threadIdx.x;
    if (e >= e_count) return;
    int src = ei[e];
    int dst = ei[e_count + e];
    int slot = atomicAdd(&g_cnt[dst], 1);
    if (slot < CAP) g_csr[(size_t)dst * CAP + slot] = src;
}

// batch sorted -> warp-aggregated atomics; separate launch after zero_kernel.
__global__ void pcnt_kernel(const int* __restrict__ batch, int n) {
    int i = blockIdx.x * blockDim.x + threadIdx.x;
    if (i >= n) return;
    int b = batch[i];
    unsigned mask = __match_any_sync(__activemask(), b);
    int leader = __ffs(mask) - 1;
    if ((int)(threadIdx.x & 31) == leader)
        atomicAdd(&g_pcnt[b], __popc(mask));
}

// ---------------- GEMM via mma.sync.m16n8k16 (fp16 in, fp32 acc) -----------
// out[r][c] = rsqrt(deg[r]+1) * sum_k hin[r][k] * W[c][k], fp16 to g_g.
// B fragments in SMEM; 1 tile (16x64) per warp — best measured config.
__global__ __launch_bounds__(256) void gemm_mma_kernel(
    const float* __restrict__ x_ext, int which, const float* __restrict__ W,
    int n)
{
    const __half2* hin = (which == 1) ? g_h1 : g_h2;

    __shared__ unsigned bs[2048];      // 8 KB of B fragments

    int tid = threadIdx.x;
#pragma unroll
    for (int i = 0; i < 8; i++) {
        int flat = tid + i * 256;          // [0,2048)
        int kc =  flat >> 9;
        int nt = (flat >> 6) & 7;
        int gg = (flat >> 3) & 7;
        int tt = (flat >> 1) & 3;
        int j  =  flat & 1;
        int col = nt * 8 + gg;
        int k   = kc * 16 + 2 * tt + 8 * j;
        __half2 h = __floats2half2_rn(W[col * 64 + k], W[col * 64 + k + 1]);
        bs[flat] = *(unsigned*)&h;
    }
    __syncthreads();

    int lane = tid & 31;
    int g = lane >> 2, t = lane & 3;

    int warp_id = (blockIdx.x * blockDim.x + tid) >> 5;
    int nwarps  = (gridDim.x * blockDim.x) >> 5;
    int ntiles  = (n + 15) >> 4;

    for (int rt = warp_id; rt < ntiles; rt += nwarps) {
        int row0 = rt * 16;
        int r_lo = row0 + g;
        int r_hi = row0 + g + 8;
        bool ok_lo = (r_lo < n), ok_hi = (r_hi < n);

        unsigned a[4][4];
        if (which == 0) {
            const float* plo = x_ext + (size_t)r_lo * 64;
            const float* phi = x_ext + (size_t)r_hi * 64;
#pragma unroll
            for (int kc = 0; kc < 4; kc++) {
                int k0 = kc * 16 + 2 * t;
                if (ok_lo) {
                    float2 v0 = *(const float2*)&plo[k0];
                    float2 v1 = *(const float2*)&plo[k0 + 8];
                    __half2 q0 = __floats2half2_rn(v0.x, v0.y);
                    __half2 q1 = __floats2half2_rn(v1.x, v1.y);
                    a[kc][0] = *(unsigned*)&q0; a[kc][2] = *(unsigned*)&q1;
                } else { a[kc][0] = 0u; a[kc][2] = 0u; }
                if (ok_hi) {
                    float2 v0 = *(const float2*)&phi[k0];
                    float2 v1 = *(const float2*)&phi[k0 + 8];
                    __half2 q0 = __floats2half2_rn(v0.x, v0.y);
                    __half2 q1 = __floats2half2_rn(v1.x, v1.y);
                    a[kc][1] = *(unsigned*)&q0; a[kc][3] = *(unsigned*)&q1;
                } else { a[kc][1] = 0u; a[kc][3] = 0u; }
            }
        } else {
            const __half2* plo = hin + (size_t)r_lo * 32;
            const __half2* phi = hin + (size_t)r_hi * 32;
#pragma unroll
            for (int kc = 0; kc < 4; kc++) {
                if (ok_lo) {
                    a[kc][0] = *(const unsigned*)&plo[kc * 8 + t];
                    a[kc][2] = *(const unsigned*)&plo[kc * 8 + t + 4];
                } else { a[kc][0] = 0u; a[kc][2] = 0u; }
                if (ok_hi) {
                    a[kc][1] = *(const unsigned*)&phi[kc * 8 + t];
                    a[kc][3] = *(const unsigned*)&phi[kc * 8 + t + 4];
                } else { a[kc][1] = 0u; a[kc][3] = 0u; }
            }
        }

        float c[8][4];
#pragma unroll
        for (int nt = 0; nt < 8; nt++) { c[nt][0]=0.f; c[nt][1]=0.f; c[nt][2]=0.f; c[nt][3]=0.f; }

#pragma unroll
        for (int kc = 0; kc < 4; kc++)
#pragma unroll
            for (int nt = 0; nt < 8; nt++) {
                uint2 bb = *(const uint2*)&bs[(((kc * 8 + nt) * 8 + g) * 4 + t) * 2];
                asm volatile(
                    "mma.sync.aligned.m16n8k16.row.col.f32.f16.f16.f32 "
                    "{%0,%1,%2,%3}, {%4,%5,%6,%7}, {%8,%9}, {%0,%1,%2,%3};"
                    : "+f"(c[nt][0]), "+f"(c[nt][1]), "+f"(c[nt][2]), "+f"(c[nt][3])
                    : "r"(a[kc][0]), "r"(a[kc][1]), "r"(a[kc][2]), "r"(a[kc][3]),
                      "r"(bb.x), "r"(bb.y));
            }

        if (ok_lo) {
            float dlo = rsqrtf((float)g_cnt[r_lo] + 1.0f);
            __half2* olo = g_g + (size_t)r_lo * 32;
#pragma unroll
            for (int nt = 0; nt < 8; nt++)
                olo[nt * 4 + t] = __floats2half2_rn(c[nt][0] * dlo, c[nt][1] * dlo);
        }
        if (ok_hi) {
            float dhi = rsqrtf((float)g_cnt[r_hi] + 1.0f);
            __half2* ohi = g_g + (size_t)r_hi * 32;
#pragma unroll
            for (int nt = 0; nt < 8; nt++)
                ohi[nt * 4 + t] = __floats2half2_rn(c[nt][2] * dhi, c[nt][3] * dhi);
        }
    }
}

// ---------------- aggregation: FOUR nodes per warp --------------------------
// Quarter-warp per node: 8 lanes x 16 B (LDG.128) cover a 128 B message row.
// One gather warp-instruction serves 4 edges (one per quarter). Eight edges
// fold fully in fp16 (pairwise tree, 7 HADD2/component) before one fp32
// convert+accumulate.
__global__ __launch_bounds__(512) void agg_kernel(
    const float* __restrict__ bias,
    const int*   __restrict__ batch,
    int mode, int n)
{
    int warp = (blockIdx.x * blockDim.x + threadIdx.x) >> 5;
    int lane = threadIdx.x & 31;
    int quad = lane >> 3;              // node within the 4
    int sub  = lane & 7;               // 16-byte column chunk
    int w = warp * 4 + quad;
    if (w >= n) return;

    const char* gbase = (const char*)g_g + sub * 16;
#define LDGU4(s) (*(const uint4*)(gbase + (size_t)((unsigned)(s) * 128u)))
#define H2(u)    (*(const __half2*)&(u))

    uint4 su = LDGU4(w);               // self loop
    float2 a0 = __half22float2(H2(su.x));
    float2 a1 = __half22float2(H2(su.y));
    float2 a2 = __half22float2(H2(su.z));
    float2 a3 = __half22float2(H2(su.w));

    int cnt  = g_cnt[w];
    int cnum = min(cnt, CAP);
    const int* lst = &g_csr[(size_t)w * CAP];

    int e = 0;
    for (; e + 8 <= cnum; e += 8) {
        int4 sa = *(const int4*)&lst[e];       // uniform within quarter-warp
        int4 sb = *(const int4*)&lst[e + 4];
        uint4 u0 = LDGU4(sa.x), u1 = LDGU4(sa.y), u2 = LDGU4(sa.z), u3 = LDGU4(sa.w);
        uint4 u4 = LDGU4(sb.x), u5 = LDGU4(sb.y), u6 = LDGU4(sb.z), u7 = LDGU4(sb.w);
        // pairwise fp16 tree over 8 edges, per 32-bit component
        __half2 sx = __hadd2(__hadd2(__hadd2(H2(u0.x), H2(u1.x)), __hadd2(H2(u2.x), H2(u3.x))),
                             __hadd2(__hadd2(H2(u4.x), H2(u5.x)), __hadd2(H2(u6.x), H2(u7.x))));
        __half2 sy = __hadd2(__hadd2(__hadd2(H2(u0.y), H2(u1.y)), __hadd2(H2(u2.y), H2(u3.y))),
                             __hadd2(__hadd2(H2(u4.y), H2(u5.y)), __hadd2(H2(u6.y), H2(u7.y))));
        __half2 sz = __hadd2(__hadd2(__hadd2(H2(u0.z), H2(u1.z)), __hadd2(H2(u2.z), H2(u3.z))),
                             __hadd2(__hadd2(H2(u4.z), H2(u5.z)), __hadd2(H2(u6.z), H2(u7.z))));
        __half2 sw = __hadd2(__hadd2(__hadd2(H2(u0.w), H2(u1.w)), __hadd2(H2(u2.w), H2(u3.w))),
                             __hadd2(__hadd2(H2(u4.w), H2(u5.w)), __hadd2(H2(u6.w), H2(u7.w))));
        float2 f0 = __half22float2(sx);
        float2 f1 = __half22float2(sy);
        float2 f2 = __half22float2(sz);
        float2 f3 = __half22float2(sw);
        a0.x += f0.x;  a0.y += f0.y;
        a1.x += f1.x;  a1.y += f1.y;
        a2.x += f2.x;  a2.y += f2.y;
        a3.x += f3.x;  a3.y += f3.y;
    }
    for (; e + 4 <= cnum; e += 4) {
        int4 sa = *(const int4*)&lst[e];
        uint4 u0 = LDGU4(sa.x), u1 = LDGU4(sa.y), u2 = LDGU4(sa.z), u3 = LDGU4(sa.w);
        __half2 sx = __hadd2(__hadd2(H2(u0.x), H2(u1.x)), __hadd2(H2(u2.x), H2(u3.x)));
        __half2 sy = __hadd2(__hadd2(H2(u0.y), H2(u1.y)), __hadd2(H2(u2.y), H2(u3.y)));
        __half2 sz = __hadd2(__hadd2(H2(u0.z), H2(u1.z)), __hadd2(H2(u2.z), H2(u3.z)));
        __half2 sw = __hadd2(__hadd2(H2(u0.w), H2(u1.w)), __hadd2(H2(u2.w), H2(u3.w)));
        float2 f0 = __half22float2(sx);
        float2 f1 = __half22float2(sy);
        float2 f2 = __half22float2(sz);
        float2 f3 = __half22float2(sw);
        a0.x += f0.x;  a0.y += f0.y;
        a1.x += f1.x;  a1.y += f1.y;
        a2.x += f2.x;  a2.y += f2.y;
        a3.x += f3.x;  a3.y += f3.y;
    }
    for (; e < cnum; e++) {
        uint4 u0 = LDGU4(lst[e]);
        float2 f0 = __half22float2(H2(u0.x));
        float2 f1 = __half22float2(H2(u0.y));
        float2 f2 = __half22float2(H2(u0.z));
        float2 f3 = __half22float2(H2(u0.w));
        a0.x += f0.x;  a0.y += f0.y;
        a1.x += f1.x;  a1.y += f1.y;
        a2.x += f2.x;  a2.y += f2.y;
        a3.x += f3.x;  a3.y += f3.y;
    }
#undef LDGU4
#undef H2

    float dv = rsqrtf((float)cnt + 1.0f);
    float4 bv0 = *(const float4*)&bias[sub * 8];
    float4 bv1 = *(const float4*)&bias[sub * 8 + 4];
    float o0 = fmaxf(fmaf(dv, a0.x, bv0.x), 0.0f);
    float o1 = fmaxf(fmaf(dv, a0.y, bv0.y), 0.0f);
    float o2 = fmaxf(fmaf(dv, a1.x, bv0.z), 0.0f);
    float o3 = fmaxf(fmaf(dv, a1.y, bv0.w), 0.0f);
    float o4 = fmaxf(fmaf(dv, a2.x, bv1.x), 0.0f);
    float o5 = fmaxf(fmaf(dv, a2.y, bv1.y), 0.0f);
    float o6 = fmaxf(fmaf(dv, a3.x, bv1.z), 0.0f);
    float o7 = fmaxf(fmaf(dv, a3.y, bv1.w), 0.0f);

    if (mode == 3) {
        int b = batch[w];
        float* pp = &g_pool[b * 64 + sub * 8];
        atomicAdd(pp,     o0);  atomicAdd(pp + 1, o1);
        atomicAdd(pp + 2, o2);  atomicAdd(pp + 3, o3);
        atomicAdd(pp + 4, o4);  atomicAdd(pp + 5, o5);
        atomicAdd(pp + 6, o6);  atomicAdd(pp + 7, o7);
    } else {
        __half2 p0 = __floats2half2_rn(o0, o1);
        __half2 p1 = __floats2half2_rn(o2, o3);
        __half2 p2 = __floats2half2_rn(o4, o5);
        __half2 p3 = __floats2half2_rn(o6, o7);
        uint4 pv = make_uint4(*(unsigned*)&p0, *(unsigned*)&p1,
                              *(unsigned*)&p2, *(unsigned*)&p3);
        char* dst = (char*)((mode == 1) ? g_h1 : g_h2) + (size_t)w * 128 + sub * 16;
        *(uint4*)dst = pv;
    }
}

// ---------------- final: out[b][o] = mean-pool(b) . Wl[o] + bl[o] -----------
__global__ void final_kernel(const float* __restrict__ Wl,
                             const float* __restrict__ bl,
                             float* __restrict__ out)
{
    int t = blockIdx.x * blockDim.x + threadIdx.x;
    if (t >= BGR * 16) return;
    int b = t >> 4, o = t & 15;
    float inv = 1.0f / fmaxf((float)g_pcnt[b], 1.0f);
    const float* pr = &g_pool[b * 64];
    const float* wr = &Wl[o * 64];
    float s = 0.0f;
#pragma unroll
    for (int k = 0; k < 64; k++) s = fmaf(pr[k], wr[k], s);
    out[t] = fmaf(s, inv, bl[o]);
}

// ---------------- launch ----------------------------------------------------
extern "C" void kernel_launch(void* const* d_in, const int* in_sizes, int n_in,
                              void* d_out, int out_size)
{
    const float* x     = (const float*)d_in[0];
    const int*   ei    = (const int*)  d_in[1];
    const int*   batch = (const int*)  d_in[2];
    const float* W1    = (const float*)d_in[3];
    const float* b1    = (const float*)d_in[4];
    const float* W2    = (const float*)d_in[5];
    const float* b2    = (const float*)d_in[6];
    const float* W3    = (const float*)d_in[7];
    const float* b3    = (const float*)d_in[8];
    const float* Wl    = (const float*)d_in[9];
    const float* bl    = (const float*)d_in[10];
    float* out = (float*)d_out;

    int n = in_sizes[0] / 64;   // 50000
    int e = in_sizes[1] / 2;    // 1250000

    int nb_n = (n + 255) / 256;
    int nb_e = (e + 255) / 256;
    int nquads = (n + 3) / 4;                  // agg: 4 nodes / warp
    int nb_a = (nquads * 32 + 511) / 512;
    int ntiles = (n + 15) / 16;
    int nb_m = (ntiles + 7) / 8;               // gemm: 1 tile / warp

    // Order: zero(1), csr(2), gemm1(3), agg1(4) <- ncu window, pcnt(5), ...
    zero_kernel<<<nb_n, 256>>>(n);
    csr_build_kernel<<<nb_e, 256>>>(ei, e);

    gemm_mma_kernel<<<nb_m, 256>>>(x, 0, W1, n);
    agg_kernel<<<nb_a, 512>>>(b1, batch, 1, n);

    pcnt_kernel<<<nb_n, 256>>>(batch, n);

    gemm_mma_kernel<<<nb_m, 256>>>(x, 1, W2, n);
    agg_kernel<<<nb_a, 512>>>(b2, batch, 2, n);

    gemm_mma_kernel<<<nb_m, 256>>>(x, 2, W3, n);
    agg_kernel<<<nb_a, 512>>>(b3, batch, 3, n);

    final_kernel<<<(BGR * 16 + 255) / 256, 256>>>(Wl, bl, out);
}

// round 15
// speedup vs baseline: 1.1724x; 1.1724x over previous
#include <cuda_runtime.h>
#include <cuda_bf16.h>
#include <cuda_fp16.h>

// Problem constants (fixed by the dataset).
#define NMAX 50000
#define CAP  64           // max in-degree bucket (Poisson mean 25; P(>64)~e-107)
#define DH   64
#define BGR  512

// ---------------- scratch (static device memory; no allocations) -----------
__device__ int     g_cnt [NMAX];                  // in-degree (excl. self loop)
__device__ int     g_csr [(size_t)NMAX * CAP];    // bucketed incoming src lists
__device__ __half2 g_h1  [(size_t)NMAX * 32];     // layer outputs (ping, fp16)
__device__ __half2 g_h2  [(size_t)NMAX * 32];     // layer outputs (pong, fp16)
__device__ __half2 g_g   [(size_t)(NMAX + 1) * 32]; // messages + zero pad row
__device__ float   g_pool[BGR * DH];              // per-graph feature sums
__device__ int     g_pcnt[BGR];                   // per-graph node counts

// ---------------- setup kernels --------------------------------------------
__global__ void zero_kernel(int n) {
    int i = blockIdx.x * blockDim.x + threadIdx.x;
    if (i < n)        g_cnt[i]  = 0;
    if (i < BGR * DH) g_pool[i] = 0.0f;
    if (i < BGR)      g_pcnt[i] = 0;
    if (i < 32)       g_g[(size_t)NMAX * 32 + i] = __floats2half2_rn(0.f, 0.f);
}

__global__ void csr_build_kernel(const int* __restrict__ ei, int e_count) {
    int e = blockIdx.x * blockDim.x + threadIdx.x;
    if (e >= e_count) return;
    int src = ei[e];
    int dst = ei[e_count + e];
    int slot = atomicAdd(&g_cnt[dst], 1);
    if (slot < CAP) g_csr[(size_t)dst * CAP + slot] = src;
}

// Pad each CSR list up to a multiple of 8 with the dummy index NMAX (whose
// message row is permanently zero), and accumulate per-graph node counts
// (batch sorted -> warp-aggregated atomics). 8 threads per node.
__global__ void pad_pcnt_kernel(const int* __restrict__ batch, int n) {
    int idx = blockIdx.x * blockDim.x + threadIdx.x;
    int i = idx >> 3, j = idx & 7;
    if (i >= n) return;
    int c = min(g_cnt[i], CAP);
    int cp = (c + 7) & ~7;              // <= CAP since CAP % 8 == 0
    int slot = c + j;
    if (slot < cp) g_csr[(size_t)i * CAP + slot] = NMAX;
    if (j == 0) {
        int b = batch[i];
        unsigned mask = __match_any_sync(__activemask(), b);
        int leader = __ffs(mask) - 1;
        if ((int)(threadIdx.x & 31) == leader)
            atomicAdd(&g_pcnt[b], __popc(mask));
    }
}

// ---------------- GEMM via mma.sync.m16n8k16 (fp16 in, fp32 acc) -----------
// out[r][c] = rsqrt(deg[r]+1) * sum_k hin[r][k] * W[c][k], fp16 to g_g.
// B fragments in SMEM; 1 tile (16x64) per warp — best measured config.
__global__ __launch_bounds__(256) void gemm_mma_kernel(
    const float* __restrict__ x_ext, int which, const float* __restrict__ W,
    int n)
{
    const __half2* hin = (which == 1) ? g_h1 : g_h2;

    __shared__ unsigned bs[2048];      // 8 KB of B fragments

    int tid = threadIdx.x;
#pragma unroll
    for (int i = 0; i < 8; i++) {
        int flat = tid + i * 256;          // [0,2048)
        int kc =  flat >> 9;
        int nt = (flat >> 6) & 7;
        int gg = (flat >> 3) & 7;
        int tt = (flat >> 1) & 3;
        int j  =  flat & 1;
        int col = nt * 8 + gg;
        int k   = kc * 16 + 2 * tt + 8 * j;
        __half2 h = __floats2half2_rn(W[col * 64 + k], W[col * 64 + k + 1]);
        bs[flat] = *(unsigned*)&h;
    }
    __syncthreads();

    int lane = tid & 31;
    int g = lane >> 2, t = lane & 3;

    int warp_id = (blockIdx.x * blockDim.x + tid) >> 5;
    int nwarps  = (gridDim.x * blockDim.x) >> 5;
    int ntiles  = (n + 15) >> 4;

    for (int rt = warp_id; rt < ntiles; rt += nwarps) {
        int row0 = rt * 16;
        int r_lo = row0 + g;
        int r_hi = row0 + g + 8;
        bool ok_lo = (r_lo < n), ok_hi = (r_hi < n);

        unsigned a[4][4];
        if (which == 0) {
            const float* plo = x_ext + (size_t)r_lo * 64;
            const float* phi = x_ext + (size_t)r_hi * 64;
#pragma unroll
            for (int kc = 0; kc < 4; kc++) {
                int k0 = kc * 16 + 2 * t;
                if (ok_lo) {
                    float2 v0 = *(const float2*)&plo[k0];
                    float2 v1 = *(const float2*)&plo[k0 + 8];
                    __half2 q0 = __floats2half2_rn(v0.x, v0.y);
                    __half2 q1 = __floats2half2_rn(v1.x, v1.y);
                    a[kc][0] = *(unsigned*)&q0; a[kc][2] = *(unsigned*)&q1;
                } else { a[kc][0] = 0u; a[kc][2] = 0u; }
                if (ok_hi) {
                    float2 v0 = *(const float2*)&phi[k0];
                    float2 v1 = *(const float2*)&phi[k0 + 8];
                    __half2 q0 = __floats2half2_rn(v0.x, v0.y);
                    __half2 q1 = __floats2half2_rn(v1.x, v1.y);
                    a[kc][1] = *(unsigned*)&q0; a[kc][3] = *(unsigned*)&q1;
                } else { a[kc][1] = 0u; a[kc][3] = 0u; }
            }
        } else {
            const __half2* plo = hin + (size_t)r_lo * 32;
            const __half2* phi = hin + (size_t)r_hi * 32;
#pragma unroll
            for (int kc = 0; kc < 4; kc++) {
                if (ok_lo) {
                    a[kc][0] = *(const unsigned*)&plo[kc * 8 + t];
                    a[kc][2] = *(const unsigned*)&plo[kc * 8 + t + 4];
                } else { a[kc][0] = 0u; a[kc][2] = 0u; }
                if (ok_hi) {
                    a[kc][1] = *(const unsigned*)&phi[kc * 8 + t];
                    a[kc][3] = *(const unsigned*)&phi[kc * 8 + t + 4];
                } else { a[kc][1] = 0u; a[kc][3] = 0u; }
            }
        }

        float c[8][4];
#pragma unroll
        for (int nt = 0; nt < 8; nt++) { c[nt][0]=0.f; c[nt][1]=0.f; c[nt][2]=0.f; c[nt][3]=0.f; }

#pragma unroll
        for (int kc = 0; kc < 4; kc++)
#pragma unroll
            for (int nt = 0; nt < 8; nt++) {
                uint2 bb = *(const uint2*)&bs[(((kc * 8 + nt) * 8 + g) * 4 + t) * 2];
                asm volatile(
                    "mma.sync.aligned.m16n8k16.row.col.f32.f16.f16.f32 "
                    "{%0,%1,%2,%3}, {%4,%5,%6,%7}, {%8,%9}, {%0,%1,%2,%3};"
                    : "+f"(c[nt][0]), "+f"(c[nt][1]), "+f"(c[nt][2]), "+f"(c[nt][3])
                    : "r"(a[kc][0]), "r"(a[kc][1]), "r"(a[kc][2]), "r"(a[kc][3]),
                      "r"(bb.x), "r"(bb.y));
            }

        if (ok_lo) {
            float dlo = rsqrtf((float)g_cnt[r_lo] + 1.0f);
            __half2* olo = g_g + (size_t)r_lo * 32;
#pragma unroll
            for (int nt = 0; nt < 8; nt++)
                olo[nt * 4 + t] = __floats2half2_rn(c[nt][0] * dlo, c[nt][1] * dlo);
        }
        if (ok_hi) {
            float dhi = rsqrtf((float)g_cnt[r_hi] + 1.0f);
            __half2* ohi = g_g + (size_t)r_hi * 32;
#pragma unroll
            for (int nt = 0; nt < 8; nt++)
                ohi[nt * 4 + t] = __floats2half2_rn(c[nt][2] * dhi, c[nt][3] * dhi);
        }
    }
}

// ---------------- aggregation: TWO nodes per warp (measured best) -----------
// Half-warp per node: 16 lanes x 8 B cover a 128 B message row; one LDG
// warp-instruction gathers one edge per half. Lists padded to multiples of 8
// with the zero-row dummy -> no tail loops. Eight edges fold fully in fp16
// (pairwise tree, validated in R14: no rel_err impact) then one fp32 add.
__global__ __launch_bounds__(512) void agg_kernel(
    const float* __restrict__ bias,
    const int*   __restrict__ batch,
    int mode, int n)
{
    int warp = (blockIdx.x * blockDim.x + threadIdx.x) >> 5;
    int lane = threadIdx.x & 31;
    int half = lane >> 4;              // which node of the pair
    int sub  = lane & 15;              // 8-byte column chunk
    int w = warp * 2 + half;
    if (w >= n) return;

    const char* gbase = (const char*)g_g + sub * 8;
#define LDGU2(s) (*(const uint2*)(gbase + (size_t)((unsigned)(s) * 128u)))
#define H2(u)    (*(const __half2*)&(u))

    uint2 su = LDGU2(w);               // self loop
    float2 ax = __half22float2(H2(su.x));
    float2 ay = __half22float2(H2(su.y));

    int cnt  = g_cnt[w];
    int cnum = min(cnt, CAP);
    int cpad = (cnum + 7) & ~7;        // padded with zero-row dummies
    const int* lst = &g_csr[(size_t)w * CAP];

    for (int e = 0; e < cpad; e += 8) {
        int4 sa = *(const int4*)&lst[e];       // uniform within half-warp
        int4 sb = *(const int4*)&lst[e + 4];
        uint2 u0 = LDGU2(sa.x), u1 = LDGU2(sa.y), u2 = LDGU2(sa.z), u3 = LDGU2(sa.w);
        uint2 u4 = LDGU2(sb.x), u5 = LDGU2(sb.y), u6 = LDGU2(sb.z), u7 = LDGU2(sb.w);
        __half2 sx = __hadd2(
            __hadd2(__hadd2(H2(u0.x), H2(u1.x)), __hadd2(H2(u2.x), H2(u3.x))),
            __hadd2(__hadd2(H2(u4.x), H2(u5.x)), __hadd2(H2(u6.x), H2(u7.x))));
        __half2 sy = __hadd2(
            __hadd2(__hadd2(H2(u0.y), H2(u1.y)), __hadd2(H2(u2.y), H2(u3.y))),
            __hadd2(__hadd2(H2(u4.y), H2(u5.y)), __hadd2(H2(u6.y), H2(u7.y))));
        float2 f0 = __half22float2(sx);
        float2 f1 = __half22float2(sy);
        ax.x += f0.x;  ax.y += f0.y;
        ay.x += f1.x;  ay.y += f1.y;
    }
#undef LDGU2
#undef H2

    float dv = rsqrtf((float)cnt + 1.0f);
    float4 bv = *(const float4*)&bias[sub * 4];
    float o0 = fmaxf(fmaf(dv, ax.x, bv.x), 0.0f);
    float o1 = fmaxf(fmaf(dv, ax.y, bv.y), 0.0f);
    float o2 = fmaxf(fmaf(dv, ay.x, bv.z), 0.0f);
    float o3 = fmaxf(fmaf(dv, ay.y, bv.w), 0.0f);

    if (mode == 3) {
        int b = batch[w];
        float* pp = &g_pool[b * 64 + sub * 4];
        atomicAdd(pp,     o0);
        atomicAdd(pp + 1, o1);
        atomicAdd(pp + 2, o2);
        atomicAdd(pp + 3, o3);
    } else {
        __half2 p0 = __floats2half2_rn(o0, o1);
        __half2 p1 = __floats2half2_rn(o2, o3);
        uint2 pv = make_uint2(*(unsigned*)&p0, *(unsigned*)&p1);
        char* dst = (char*)((mode == 1) ? g_h1 : g_h2) + (size_t)w * 128 + sub * 8;
        *(uint2*)dst = pv;
    }
}

// ---------------- final: out[b][o] = mean-pool(b) . Wl[o] + bl[o] -----------
__global__ void final_kernel(const float* __restrict__ Wl,
                             const float* __restrict__ bl,
                             float* __restrict__ out)
{
    int t = blockIdx.x * blockDim.x + threadIdx.x;
    if (t >= BGR * 16) return;
    int b = t >> 4, o = t & 15;
    float inv = 1.0f / fmaxf((float)g_pcnt[b], 1.0f);
    const float* pr = &g_pool[b * 64];
    const float* wr = &Wl[o * 64];
    float s = 0.0f;
#pragma unroll
    for (int k = 0; k < 64; k++) s = fmaf(pr[k], wr[k], s);
    out[t] = fmaf(s, inv, bl[o]);
}

// ---------------- launch ----------------------------------------------------
extern "C" void kernel_launch(void* const* d_in, const int* in_sizes, int n_in,
                              void* d_out, int out_size)
{
    const float* x     = (const float*)d_in[0];
    const int*   ei    = (const int*)  d_in[1];
    const int*   batch = (const int*)  d_in[2];
    const float* W1    = (const float*)d_in[3];
    const float* b1    = (const float*)d_in[4];
    const float* W2    = (const float*)d_in[5];
    const float* b2    = (const float*)d_in[6];
    const float* W3    = (const float*)d_in[7];
    const float* b3    = (const float*)d_in[8];
    const float* Wl    = (const float*)d_in[9];
    const float* bl    = (const float*)d_in[10];
    float* out = (float*)d_out;

    int n = in_sizes[0] / 64;   // 50000
    int e = in_sizes[1] / 2;    // 1250000

    int nb_n = (n + 255) / 256;
    int nb_e = (e + 255) / 256;
    int nb_p = (n * 8 + 255) / 256;            // pad+pcnt: 8 threads / node
    int npairs = (n + 1) / 2;                  // agg: 2 nodes / warp
    int nb_a = (npairs * 32 + 511) / 512;
    int ntiles = (n + 15) / 16;
    int nb_m = (ntiles + 7) / 8;               // gemm: 1 tile / warp

    zero_kernel<<<nb_n, 256>>>(n);
    csr_build_kernel<<<nb_e, 256>>>(ei, e);
    pad_pcnt_kernel<<<nb_p, 256>>>(batch, n);  // must precede agg1

    gemm_mma_kernel<<<nb_m, 256>>>(x, 0, W1, n);
    agg_kernel<<<nb_a, 512>>>(b1, batch, 1, n);

    gemm_mma_kernel<<<nb_m, 256>>>(x, 1, W2, n);
    agg_kernel<<<nb_a, 512>>>(b2, batch, 2, n);

    gemm_mma_kernel<<<nb_m, 256>>>(x, 2, W3, n);
    agg_kernel<<<nb_a, 512>>>(b3, batch, 3, n);

    final_kernel<<<(BGR * 16 + 255) / 256, 256>>>(Wl, bl, out);
}

// round 16
// speedup vs baseline: 1.2637x; 1.0779x over previous
#include <cuda_runtime.h>
#include <cuda_bf16.h>
#include <cuda_fp16.h>

// Problem constants (fixed by the dataset).
#define NMAX 50000
#define CAP  64           // max in-degree bucket (Poisson mean 25; P(>64)~e-107)
#define DH   64
#define BGR  512

// ---------------- scratch (static device memory; no allocations) -----------
__device__ int     g_cnt [NMAX];                  // in-degree (excl. self loop)
__device__ int     g_csr [(size_t)NMAX * CAP];    // bucketed incoming src lists
__device__ __half2 g_h1  [(size_t)NMAX * 32];     // layer outputs (ping, fp16)
__device__ __half2 g_h2  [(size_t)NMAX * 32];     // layer outputs (pong, fp16)
__device__ __half2 g_g   [(size_t)NMAX * 32];     // dinv-scaled GEMM output
__device__ float   g_pool[BGR * DH];              // per-graph feature sums

// ---------------- setup kernels --------------------------------------------
__global__ void zero_kernel(int n) {
    int i = blockIdx.x * blockDim.x + threadIdx.x;
    if (i < n)        g_cnt[i]  = 0;
    if (i < BGR * DH) g_pool[i] = 0.0f;
}

// Two edges per thread (int2 loads; e_count is even and 8B-aligned offsets).
__global__ void csr_build_kernel(const int* __restrict__ ei, int e_count) {
    int i = blockIdx.x * blockDim.x + threadIdx.x;
    int e = i * 2;
    if (e >= e_count) return;
    if (e + 1 < e_count) {
        int2 s2 = *(const int2*)&ei[e];
        int2 d2 = *(const int2*)&ei[e_count + e];
        int slot0 = atomicAdd(&g_cnt[d2.x], 1);
        if (slot0 < CAP) g_csr[(size_t)d2.x * CAP + slot0] = s2.x;
        int slot1 = atomicAdd(&g_cnt[d2.y], 1);
        if (slot1 < CAP) g_csr[(size_t)d2.y * CAP + slot1] = s2.y;
    } else {
        int src = ei[e];
        int dst = ei[e_count + e];
        int slot = atomicAdd(&g_cnt[dst], 1);
        if (slot < CAP) g_csr[(size_t)dst * CAP + slot] = src;
    }
}

// ---------------- GEMM via mma.sync.m16n8k16 (fp16 in, fp32 acc) -----------
// out[r][c] = rsqrt(deg[r]+1) * sum_k hin[r][k] * W[c][k], fp16 to g_g.
// B fragments in SMEM; 1 tile (16x64) per warp — best measured config.
__global__ __launch_bounds__(256) void gemm_mma_kernel(
    const float* __restrict__ x_ext, int which, const float* __restrict__ W,
    int n)
{
    const __half2* hin = (which == 1) ? g_h1 : g_h2;

    __shared__ unsigned bs[2048];      // 8 KB of B fragments

    int tid = threadIdx.x;
#pragma unroll
    for (int i = 0; i < 8; i++) {
        int flat = tid + i * 256;          // [0,2048)
        int kc =  flat >> 9;
        int nt = (flat >> 6) & 7;
        int gg = (flat >> 3) & 7;
        int tt = (flat >> 1) & 3;
        int j  =  flat & 1;
        int col = nt * 8 + gg;
        int k   = kc * 16 + 2 * tt + 8 * j;
        __half2 h = __floats2half2_rn(W[col * 64 + k], W[col * 64 + k + 1]);
        bs[flat] = *(unsigned*)&h;
    }
    __syncthreads();

    int lane = tid & 31;
    int g = lane >> 2, t = lane & 3;

    int warp_id = (blockIdx.x * blockDim.x + tid) >> 5;
    int nwarps  = (gridDim.x * blockDim.x) >> 5;
    int ntiles  = (n + 15) >> 4;

    for (int rt = warp_id; rt < ntiles; rt += nwarps) {
        int row0 = rt * 16;
        int r_lo = row0 + g;
        int r_hi = row0 + g + 8;
        bool ok_lo = (r_lo < n), ok_hi = (r_hi < n);

        unsigned a[4][4];
        if (which == 0) {
            const float* plo = x_ext + (size_t)r_lo * 64;
            const float* phi = x_ext + (size_t)r_hi * 64;
#pragma unroll
            for (int kc = 0; kc < 4; kc++) {
                int k0 = kc * 16 + 2 * t;
                if (ok_lo) {
                    float2 v0 = *(const float2*)&plo[k0];
                    float2 v1 = *(const float2*)&plo[k0 + 8];
                    __half2 q0 = __floats2half2_rn(v0.x, v0.y);
                    __half2 q1 = __floats2half2_rn(v1.x, v1.y);
                    a[kc][0] = *(unsigned*)&q0; a[kc][2] = *(unsigned*)&q1;
                } else { a[kc][0] = 0u; a[kc][2] = 0u; }
                if (ok_hi) {
                    float2 v0 = *(const float2*)&phi[k0];
                    float2 v1 = *(const float2*)&phi[k0 + 8];
                    __half2 q0 = __floats2half2_rn(v0.x, v0.y);
                    __half2 q1 = __floats2half2_rn(v1.x, v1.y);
                    a[kc][1] = *(unsigned*)&q0; a[kc][3] = *(unsigned*)&q1;
                } else { a[kc][1] = 0u; a[kc][3] = 0u; }
            }
        } else {
            const __half2* plo = hin + (size_t)r_lo * 32;
            const __half2* phi = hin + (size_t)r_hi * 32;
#pragma unroll
            for (int kc = 0; kc < 4; kc++) {
                if (ok_lo) {
                    a[kc][0] = *(const unsigned*)&plo[kc * 8 + t];
                    a[kc][2] = *(const unsigned*)&plo[kc * 8 + t + 4];
                } else { a[kc][0] = 0u; a[kc][2] = 0u; }
                if (ok_hi) {
                    a[kc][1] = *(const unsigned*)&phi[kc * 8 + t];
                    a[kc][3] = *(const unsigned*)&phi[kc * 8 + t + 4];
                } else { a[kc][1] = 0u; a[kc][3] = 0u; }
            }
        }

        float c[8][4];
#pragma unroll
        for (int nt = 0; nt < 8; nt++) { c[nt][0]=0.f; c[nt][1]=0.f; c[nt][2]=0.f; c[nt][3]=0.f; }

#pragma unroll
        for (int kc = 0; kc < 4; kc++)
#pragma unroll
            for (int nt = 0; nt < 8; nt++) {
                uint2 bb = *(const uint2*)&bs[(((kc * 8 + nt) * 8 + g) * 4 + t) * 2];
                asm volatile(
                    "mma.sync.aligned.m16n8k16.row.col.f32.f16.f16.f32 "
                    "{%0,%1,%2,%3}, {%4,%5,%6,%7}, {%8,%9}, {%0,%1,%2,%3};"
                    : "+f"(c[nt][0]), "+f"(c[nt][1]), "+f"(c[nt][2]), "+f"(c[nt][3])
                    : "r"(a[kc][0]), "r"(a[kc][1]), "r"(a[kc][2]), "r"(a[kc][3]),
                      "r"(bb.x), "r"(bb.y));
            }

        if (ok_lo) {
            float dlo = rsqrtf((float)g_cnt[r_lo] + 1.0f);
            __half2* olo = g_g + (size_t)r_lo * 32;
#pragma unroll
            for (int nt = 0; nt < 8; nt++)
                olo[nt * 4 + t] = __floats2half2_rn(c[nt][0] * dlo, c[nt][1] * dlo);
        }
        if (ok_hi) {
            float dhi = rsqrtf((float)g_cnt[r_hi] + 1.0f);
            __half2* ohi = g_g + (size_t)r_hi * 32;
#pragma unroll
            for (int nt = 0; nt < 8; nt++)
                ohi[nt * 4 + t] = __floats2half2_rn(c[nt][2] * dhi, c[nt][3] * dhi);
        }
    }
}

// ---------------- aggregation: TWO nodes per warp (R13 measured best) -------
// Half-warp per node: 16 lanes x 8 B cover a 128 B message row. One LDG
// warp-instruction gathers one edge per half. Tree-of-4 fp16 folds + fp32
// accumulate (R13 structure). Mode 3 folds the two nodes' outputs across
// half-warps when they share a graph (common: ~98 nodes/graph) -> half the
// pool atomics.
__global__ __launch_bounds__(512) void agg_kernel(
    const float* __restrict__ bias,
    const int*   __restrict__ batch,
    int mode, int n)
{
    int warp = (blockIdx.x * blockDim.x + threadIdx.x) >> 5;
    int lane = threadIdx.x & 31;
    int half = lane >> 4;              // which node of the pair
    int sub  = lane & 15;              // 8-byte column chunk
    int w = warp * 2 + half;
    if (w >= n) return;

    const char* gbase = (const char*)g_g + sub * 8;
#define LDGU2(s) (*(const uint2*)(gbase + (size_t)((unsigned)(s) * 128u)))
#define H2(u)    (*(const __half2*)&(u))

    uint2 su = LDGU2(w);               // self loop
    float2 accx = __half22float2(H2(su.x));
    float2 accy = __half22float2(H2(su.y));
    float2 accx2 = make_float2(0.f, 0.f), accy2 = make_float2(0.f, 0.f);

    int cnt  = g_cnt[w];
    int cnum = min(cnt, CAP);
    const int* lst = &g_csr[(size_t)w * CAP];

    int e = 0;
    for (; e + 8 <= cnum; e += 8) {
        int4 sa = *(const int4*)&lst[e];       // uniform within half-warp
        int4 sb = *(const int4*)&lst[e + 4];
        uint2 u0 = LDGU2(sa.x), u1 = LDGU2(sa.y), u2 = LDGU2(sa.z), u3 = LDGU2(sa.w);
        uint2 u4 = LDGU2(sb.x), u5 = LDGU2(sb.y), u6 = LDGU2(sb.z), u7 = LDGU2(sb.w);
        __half2 sx0 = __hadd2(__hadd2(H2(u0.x), H2(u1.x)), __hadd2(H2(u2.x), H2(u3.x)));
        __half2 sy0 = __hadd2(__hadd2(H2(u0.y), H2(u1.y)), __hadd2(H2(u2.y), H2(u3.y)));
        __half2 sx1 = __hadd2(__hadd2(H2(u4.x), H2(u5.x)), __hadd2(H2(u6.x), H2(u7.x)));
        __half2 sy1 = __hadd2(__hadd2(H2(u4.y), H2(u5.y)), __hadd2(H2(u6.y), H2(u7.y)));
        float2 f0 = __half22float2(sx0);
        float2 f1 = __half22float2(sy0);
        float2 f2 = __half22float2(sx1);
        float2 f3 = __half22float2(sy1);
        accx.x  += f0.x;  accx.y  += f0.y;
        accy.x  += f1.x;  accy.y  += f1.y;
        accx2.x += f2.x;  accx2.y += f2.y;
        accy2.x += f3.x;  accy2.y += f3.y;
    }
    for (; e + 4 <= cnum; e += 4) {
        int4 sa = *(const int4*)&lst[e];
        uint2 u0 = LDGU2(sa.x), u1 = LDGU2(sa.y), u2 = LDGU2(sa.z), u3 = LDGU2(sa.w);
        __half2 sx0 = __hadd2(__hadd2(H2(u0.x), H2(u1.x)), __hadd2(H2(u2.x), H2(u3.x)));
        __half2 sy0 = __hadd2(__hadd2(H2(u0.y), H2(u1.y)), __hadd2(H2(u2.y), H2(u3.y)));
        float2 f0 = __half22float2(sx0);
        float2 f1 = __half22float2(sy0);
        accx.x += f0.x;  accx.y += f0.y;
        accy.x += f1.x;  accy.y += f1.y;
    }
    for (; e < cnum; e++) {
        uint2 u0 = LDGU2(lst[e]);
        float2 f0 = __half22float2(H2(u0.x));
        float2 f1 = __half22float2(H2(u0.y));
        accx.x += f0.x;  accx.y += f0.y;
        accy.x += f1.x;  accy.y += f1.y;
    }
    accx.x += accx2.x;  accx.y += accx2.y;
    accy.x += accy2.x;  accy.y += accy2.y;
#undef LDGU2
#undef H2

    float dv = rsqrtf((float)cnt + 1.0f);
    float4 bv = *(const float4*)&bias[sub * 4];
    float o0 = fmaxf(fmaf(dv, accx.x, bv.x), 0.0f);
    float o1 = fmaxf(fmaf(dv, accx.y, bv.y), 0.0f);
    float o2 = fmaxf(fmaf(dv, accy.x, bv.z), 0.0f);
    float o3 = fmaxf(fmaf(dv, accy.y, bv.w), 0.0f);

    if (mode == 3) {
        int b = batch[w];
        // If the whole warp is active and both halves share a graph, fold the
        // two nodes' outputs (exact fp32 adds) and let half 0 issue atomics.
        if (warp * 2 + 1 < n) {
            int bp = __shfl_xor_sync(0xffffffffu, b, 16);
            float p0 = __shfl_xor_sync(0xffffffffu, o0, 16);
            float p1 = __shfl_xor_sync(0xffffffffu, o1, 16);
            float p2 = __shfl_xor_sync(0xffffffffu, o2, 16);
            float p3 = __shfl_xor_sync(0xffffffffu, o3, 16);
            if (bp == b) {
                if (half == 0) {
                    float* pp = &g_pool[b * 64 + sub * 4];
                    atomicAdd(pp,     o0 + p0);
                    atomicAdd(pp + 1, o1 + p1);
                    atomicAdd(pp + 2, o2 + p2);
                    atomicAdd(pp + 3, o3 + p3);
                }
                return;
            }
        }
        float* pp = &g_pool[b * 64 + sub * 4];
        atomicAdd(pp,     o0);
        atomicAdd(pp + 1, o1);
        atomicAdd(pp + 2, o2);
        atomicAdd(pp + 3, o3);
    } else {
        __half2 p0 = __floats2half2_rn(o0, o1);
        __half2 p1 = __floats2half2_rn(o2, o3);
        uint2 pv = make_uint2(*(unsigned*)&p0, *(unsigned*)&p1);
        char* dst = (char*)((mode == 1) ? g_h1 : g_h2) + (size_t)w * 128 + sub * 8;
        *(uint2*)dst = pv;
    }
}

// ---------------- final: out[b][o] = mean-pool(b) . Wl[o] + bl[o] -----------
// Node counts per graph via binary search in the sorted batch array
// (replaces the pcnt kernel + g_pcnt array).
__global__ void final_kernel(const int* __restrict__ batch, int n,
                             const float* __restrict__ Wl,
                             const float* __restrict__ bl,
                             float* __restrict__ out)
{
    int t = blockIdx.x * blockDim.x + threadIdx.x;
    if (t >= BGR * 16) return;
    int b = t >> 4, o = t & 15;

    int lo = 0, hi = n;                 // first index with batch[i] >= b
    while (lo < hi) { int m = (lo + hi) >> 1; if (batch[m] < b) lo = m + 1; else hi = m; }
    int start = lo;
    hi = n;                             // first index with batch[i] > b
    while (lo < hi) { int m = (lo + hi) >> 1; if (batch[m] <= b) lo = m + 1; else hi = m; }
    int cntb = lo - start;

    float inv = 1.0f / fmaxf((float)cntb, 1.0f);
    const float* pr = &g_pool[b * 64];
    const float* wr = &Wl[o * 64];
    float s = 0.0f;
#pragma unroll
    for (int k = 0; k < 64; k++) s = fmaf(pr[k], wr[k], s);
    out[t] = fmaf(s, inv, bl[o]);
}

// ---------------- launch ----------------------------------------------------
extern "C" void kernel_launch(void* const* d_in, const int* in_sizes, int n_in,
                              void* d_out, int out_size)
{
    const float* x     = (const float*)d_in[0];
    const int*   ei    = (const int*)  d_in[1];
    const int*   batch = (const int*)  d_in[2];
    const float* W1    = (const float*)d_in[3];
    const float* b1    = (const float*)d_in[4];
    const float* W2    = (const float*)d_in[5];
    const float* b2    = (const float*)d_in[6];
    const float* W3    = (const float*)d_in[7];
    const float* b3    = (const float*)d_in[8];
    const float* Wl    = (const float*)d_in[9];
    const float* bl    = (const float*)d_in[10];
    float* out = (float*)d_out;

    int n = in_sizes[0] / 64;   // 50000
    int e = in_sizes[1] / 2;    // 1250000

    int nb_n = (n + 255) / 256;
    int nb_e = ((e + 1) / 2 + 255) / 256;      // csr: 2 edges / thread
    int npairs = (n + 1) / 2;                  // agg: 2 nodes / warp
    int nb_a = (npairs * 32 + 511) / 512;
    int ntiles = (n + 15) / 16;
    int nb_m = (ntiles + 7) / 8;               // gemm: 1 tile / warp

    // Order: zero(1), csr(2), gemm1(3), agg1(4) <- ncu window, ...
    zero_kernel<<<nb_n, 256>>>(n);
    csr_build_kernel<<<nb_e, 256>>>(ei, e);

    gemm_mma_kernel<<<nb_m, 256>>>(x, 0, W1, n);
    agg_kernel<<<nb_a, 512>>>(b1, batch, 1, n);

    gemm_mma_kernel<<<nb_m, 256>>>(x, 1, W2, n);
    agg_kernel<<<nb_a, 512>>>(b2, batch, 2, n);

    gemm_mma_kernel<<<nb_m, 256>>>(x, 2, W3, n);
    agg_kernel<<<nb_a, 512>>>(b3, batch, 3, n);

    final_kernel<<<(BGR * 16 + 255) / 256, 256>>>(batch, n, Wl, bl, out);
}